// round 6
// baseline (speedup 1.0000x reference)
#include <cuda_runtime.h>
#include <cuda_bf16.h>
#include <math.h>
#include <stdint.h>

// Problem constants (fixed by the dataset)
#define MAXN 50000
#define MAXE 800000
#define FDIM 128
#define HDIM 256
#define LDIM 64
#define NGRAPH 500

// ---------------- static scratch (no allocs allowed) ----------------
__device__ float g_bufA[(size_t)MAXN * HDIM];
__device__ float g_bufB[(size_t)MAXN * HDIM];
__device__ int   g_counts[MAXN];
__device__ int   g_rowptr[MAXN + 1];
__device__ int   g_wpos[MAXN];
__device__ int   g_csr[MAXE];
__device__ float g_wcsr[MAXE];       // dinv[src] per CSR slot
__device__ float g_dinv[MAXN];
__device__ float g_sums[NGRAPH * HDIM];
__device__ float g_gcnt[NGRAPH];

__device__ __forceinline__ uint32_t smem_u32(const void* p) {
    uint32_t a;
    asm("{ .reg .u64 t; cvta.to.shared.u64 t, %1; cvt.u32.u64 %0, t; }" : "=r"(a) : "l"(p));
    return a;
}

#define LDSM_X4(r0, r1, r2, r3, addr) \
    asm volatile("ldmatrix.sync.aligned.m8n8.x4.shared.b16 {%0,%1,%2,%3}, [%4];" \
        : "=r"(r0), "=r"(r1), "=r"(r2), "=r"(r3) : "r"(addr))

#define LDSM_X4T(r0, r1, r2, r3, addr) \
    asm volatile("ldmatrix.sync.aligned.m8n8.x4.trans.shared.b16 {%0,%1,%2,%3}, [%4];" \
        : "=r"(r0), "=r"(r1), "=r"(r2), "=r"(r3) : "r"(addr))

#define MMA_BF16(c, a, b) \
    asm volatile("mma.sync.aligned.m16n8k16.row.col.f32.bf16.bf16.f32 " \
        "{%0,%1,%2,%3}, {%4,%5,%6,%7}, {%8,%9}, {%0,%1,%2,%3};" \
        : "+f"((c)[0]), "+f"((c)[1]), "+f"((c)[2]), "+f"((c)[3]) \
        : "r"((a)[0]), "r"((a)[1]), "r"((a)[2]), "r"((a)[3]), "r"((b)[0]), "r"((b)[1]))

// ---------------- degree / CSR build ----------------
__global__ void k_count(const int* __restrict__ dst, int E) {
    int e = blockIdx.x * blockDim.x + threadIdx.x;
    if (e < E) atomicAdd(&g_counts[dst[e]], 1);
}

__global__ void k_dinv(int N) {
    int i = blockIdx.x * blockDim.x + threadIdx.x;
    if (i < N) g_dinv[i] = rsqrtf((float)g_counts[i] + 1.0f);  // +1 self-loop
}

// single-block exclusive scan of g_counts -> g_rowptr (+ copy to g_wpos)
__global__ void k_scan(int N, int E) {
    __shared__ int sdata[1024];
    __shared__ int carry_s;
    int tid = threadIdx.x;
    if (tid == 0) carry_s = 0;
    __syncthreads();
    for (int base = 0; base < N; base += 1024) {
        int i = base + tid;
        int v = (i < N) ? g_counts[i] : 0;
        sdata[tid] = v;
        __syncthreads();
        #pragma unroll
        for (int off = 1; off < 1024; off <<= 1) {
            int t2 = (tid >= off) ? sdata[tid - off] : 0;
            __syncthreads();
            sdata[tid] += t2;
            __syncthreads();
        }
        int incl = sdata[tid];
        int excl = incl - v + carry_s;
        if (i < N) { g_rowptr[i] = excl; g_wpos[i] = excl; }
        __syncthreads();
        if (tid == 1023) carry_s += incl;
        __syncthreads();
    }
    if (tid == 0) g_rowptr[N] = E;
}

__global__ void k_fill(const int* __restrict__ src, const int* __restrict__ dst, int E) {
    int e = blockIdx.x * blockDim.x + threadIdx.x;
    if (e < E) {
        int s = src[e];
        int p = atomicAdd(&g_wpos[dst[e]], 1);
        g_csr[p]  = s;
        g_wcsr[p] = g_dinv[s];
    }
}

// ---------------- GCN aggregation: warp-per-node, float4 vectorized --------
template <int V>
__global__ void k_agg(const float* __restrict__ in, float* __restrict__ out, int N) {
    int warp = (blockIdx.x * blockDim.x + threadIdx.x) >> 5;
    if (warp >= N) return;
    int lane = threadIdx.x & 31;
    const int F = V * 128;
    int d = warp;
    float dv = g_dinv[d];

    float4 acc[V];
    const float4* selfrow = (const float4*)(in + (size_t)d * F) + lane;
    #pragma unroll
    for (int v = 0; v < V; v++) {
        float4 r = __ldg(selfrow + v * 32);
        acc[v] = make_float4(dv * r.x, dv * r.y, dv * r.z, dv * r.w);
    }

    int beg = g_rowptr[d], end = g_rowptr[d + 1];
    int   s_nx = 0; float w_nx = 0.0f;
    if (beg < end) { s_nx = __ldg(&g_csr[beg]); w_nx = __ldg(&g_wcsr[beg]); }
    for (int j = beg; j < end; j++) {
        int   s = s_nx;
        float w = w_nx;
        if (j + 1 < end) { s_nx = __ldg(&g_csr[j + 1]); w_nx = __ldg(&g_wcsr[j + 1]); }
        const float4* row = (const float4*)(in + (size_t)s * F) + lane;
        #pragma unroll
        for (int v = 0; v < V; v++) {
            float4 r = __ldg(row + v * 32);
            acc[v].x = fmaf(w, r.x, acc[v].x);
            acc[v].y = fmaf(w, r.y, acc[v].y);
            acc[v].z = fmaf(w, r.z, acc[v].z);
            acc[v].w = fmaf(w, r.w, acc[v].w);
        }
    }

    float4* orow = (float4*)(out + (size_t)d * F) + lane;
    #pragma unroll
    for (int v = 0; v < V; v++) {
        float4 o = make_float4(dv * acc[v].x, dv * acc[v].y, dv * acc[v].z, dv * acc[v].w);
        orow[v * 32] = o;
    }
}

// =================== bf16-split tensor-core GEMM (mma.sync) ===================
// C[M, 256] = relu(A[M, K] @ W[K, 256] + bias)
// 3-pass bf16 split: D = Ahi*Whi + Alo*Whi + Ahi*Wlo, fp32 accumulate in regs.
// CTA tile 128x128 (grid.x = 2 covers N=256), 8 warps in 4(M) x 2(N),
// warp tile 32x64. K chunked by 32.
#define ASTR 40     // A smem row stride in bf16 (32 data + 8 pad)
#define BSTR 136    // B smem row stride in bf16 (128 data + 8 pad)

__global__ __launch_bounds__(256, 1)
void k_gemm_mma(const float* __restrict__ A, const float* __restrict__ W,
                const float* __restrict__ bias, float* __restrict__ C,
                int M, int K) {
    __shared__ __align__(16) __nv_bfloat16 sAh[128 * ASTR];
    __shared__ __align__(16) __nv_bfloat16 sAl[128 * ASTR];
    __shared__ __align__(16) __nv_bfloat16 sBh[32 * BSTR];
    __shared__ __align__(16) __nv_bfloat16 sBl[32 * BSTR];

    const int tid  = threadIdx.x;
    const int lane = tid & 31;
    const int warp = tid >> 5;
    const int wm   = warp & 3;     // 0..3 (M dir)
    const int wn   = warp >> 2;    // 0..1 (N dir)
    const int brow = blockIdx.y * 128;
    const int bcol = blockIdx.x * 128;

    float c[2][8][4];
    #pragma unroll
    for (int mi = 0; mi < 2; mi++)
        #pragma unroll
        for (int nj = 0; nj < 8; nj++)
            #pragma unroll
            for (int q = 0; q < 4; q++) c[mi][nj][q] = 0.0f;

    const uint32_t aAh = smem_u32(sAh), aAl = smem_u32(sAl);
    const uint32_t aBh = smem_u32(sBh), aBl = smem_u32(sBl);

    for (int kc = 0; kc < K; kc += 32) {
        // ---- stage A chunk: 128x32 fp32 -> bf16 hi/lo ----
        #pragma unroll
        for (int i = 0; i < 4; i++) {
            int idx  = tid + i * 256;
            int row  = idx >> 3;
            int col4 = (idx & 7) * 4;
            int gm   = brow + row;
            float4 v = make_float4(0.f, 0.f, 0.f, 0.f);
            if (gm < M) v = __ldg((const float4*)(A + (size_t)gm * K + kc + col4));
            __nv_bfloat16 h0 = __float2bfloat16(v.x), h1 = __float2bfloat16(v.y);
            __nv_bfloat16 h2 = __float2bfloat16(v.z), h3 = __float2bfloat16(v.w);
            __nv_bfloat162 hp0; hp0.x = h0; hp0.y = h1;
            __nv_bfloat162 hp1; hp1.x = h2; hp1.y = h3;
            __nv_bfloat162 lp0; lp0.x = __float2bfloat16(v.x - __bfloat162float(h0));
            lp0.y = __float2bfloat16(v.y - __bfloat162float(h1));
            __nv_bfloat162 lp1; lp1.x = __float2bfloat16(v.z - __bfloat162float(h2));
            lp1.y = __float2bfloat16(v.w - __bfloat162float(h3));
            int o = row * ASTR + col4;
            *(__nv_bfloat162*)&sAh[o]     = hp0;
            *(__nv_bfloat162*)&sAh[o + 2] = hp1;
            *(__nv_bfloat162*)&sAl[o]     = lp0;
            *(__nv_bfloat162*)&sAl[o + 2] = lp1;
        }
        // ---- stage B chunk: W[kc..kc+32][bcol..bcol+128] -> bf16 hi/lo, [k][n] ----
        #pragma unroll
        for (int i = 0; i < 4; i++) {
            int idx  = tid + i * 256;
            int kr   = idx >> 5;
            int col4 = (idx & 31) * 4;
            float4 v = __ldg((const float4*)(W + (size_t)(kc + kr) * 256 + bcol + col4));
            __nv_bfloat16 h0 = __float2bfloat16(v.x), h1 = __float2bfloat16(v.y);
            __nv_bfloat16 h2 = __float2bfloat16(v.z), h3 = __float2bfloat16(v.w);
            __nv_bfloat162 hp0; hp0.x = h0; hp0.y = h1;
            __nv_bfloat162 hp1; hp1.x = h2; hp1.y = h3;
            __nv_bfloat162 lp0; lp0.x = __float2bfloat16(v.x - __bfloat162float(h0));
            lp0.y = __float2bfloat16(v.y - __bfloat162float(h1));
            __nv_bfloat162 lp1; lp1.x = __float2bfloat16(v.z - __bfloat162float(h2));
            lp1.y = __float2bfloat16(v.w - __bfloat162float(h3));
            int o = kr * BSTR + col4;
            *(__nv_bfloat162*)&sBh[o]     = hp0;
            *(__nv_bfloat162*)&sBh[o + 2] = hp1;
            *(__nv_bfloat162*)&sBl[o]     = lp0;
            *(__nv_bfloat162*)&sBl[o + 2] = lp1;
        }
        __syncthreads();

        #pragma unroll
        for (int ks = 0; ks < 2; ks++) {
            // A fragments (row-major, ldmatrix x4)
            uint32_t ah[2][4], al[2][4];
            #pragma unroll
            for (int mi = 0; mi < 2; mi++) {
                int row = wm * 32 + mi * 16 + (lane & 15);
                int col = ks * 16 + (lane >> 4) * 8;
                uint32_t off = (uint32_t)(row * ASTR + col) * 2;
                LDSM_X4(ah[mi][0], ah[mi][1], ah[mi][2], ah[mi][3], aAh + off);
                LDSM_X4(al[mi][0], al[mi][1], al[mi][2], al[mi][3], aAl + off);
            }
            // B fragments (col-major via trans from [k][n] smem)
            uint32_t bh[8][2], bl[8][2];
            #pragma unroll
            for (int p = 0; p < 4; p++) {
                int kr  = ks * 16 + (lane & 15);
                int col = wn * 64 + p * 16 + (lane >> 4) * 8;
                uint32_t off = (uint32_t)(kr * BSTR + col) * 2;
                LDSM_X4T(bh[2 * p][0], bh[2 * p][1], bh[2 * p + 1][0], bh[2 * p + 1][1], aBh + off);
                LDSM_X4T(bl[2 * p][0], bl[2 * p][1], bl[2 * p + 1][0], bl[2 * p + 1][1], aBl + off);
            }
            // 3 split passes
            #pragma unroll
            for (int mi = 0; mi < 2; mi++)
                #pragma unroll
                for (int nj = 0; nj < 8; nj++) {
                    MMA_BF16(c[mi][nj], ah[mi], bh[nj]);
                    MMA_BF16(c[mi][nj], al[mi], bh[nj]);
                    MMA_BF16(c[mi][nj], ah[mi], bl[nj]);
                }
        }
        __syncthreads();
    }

    // ---- epilogue: bias + relu -> global ----
    #pragma unroll
    for (int mi = 0; mi < 2; mi++) {
        int m0 = brow + wm * 32 + mi * 16 + (lane >> 2);
        #pragma unroll
        for (int nj = 0; nj < 8; nj++) {
            int n0 = bcol + wn * 64 + nj * 8 + (lane & 3) * 2;
            float bb0 = __ldg(&bias[n0]);
            float bb1 = __ldg(&bias[n0 + 1]);
            if (m0 < M) {
                float2 v;
                v.x = fmaxf(c[mi][nj][0] + bb0, 0.0f);
                v.y = fmaxf(c[mi][nj][1] + bb1, 0.0f);
                *(float2*)(C + (size_t)m0 * 256 + n0) = v;
            }
            if (m0 + 8 < M) {
                float2 v;
                v.x = fmaxf(c[mi][nj][2] + bb0, 0.0f);
                v.y = fmaxf(c[mi][nj][3] + bb1, 0.0f);
                *(float2*)(C + (size_t)(m0 + 8) * 256 + n0) = v;
            }
        }
    }
}

// ---------------- mean pool (batch is sorted) ----------------
#define POOL_CHUNK 64
__global__ void k_pool(const float* __restrict__ h, const int* __restrict__ batch, int N) {
    int f  = threadIdx.x;
    int n0 = blockIdx.x * POOL_CHUNK;
    if (n0 >= N) return;
    int n1 = min(n0 + POOL_CHUNK, N);
    int gcur = batch[n0];
    float acc = 0.0f;
    int c = 0;
    for (int n = n0; n < n1; n++) {
        int g = batch[n];
        if (g != gcur) {
            atomicAdd(&g_sums[gcur * HDIM + f], acc);
            if (f == 0) atomicAdd(&g_gcnt[gcur], (float)c);
            acc = 0.0f; c = 0; gcur = g;
        }
        acc += h[(size_t)n * HDIM + f];
        c++;
    }
    atomicAdd(&g_sums[gcur * HDIM + f], acc);
    if (f == 0) atomicAdd(&g_gcnt[gcur], (float)c);
}

// ---------------- heads: mu / logvar ----------------
__global__ void k_head(const float* __restrict__ Wmu, const float* __restrict__ bmu,
                       const float* __restrict__ Wlv, const float* __restrict__ blv,
                       float* __restrict__ out, int G) {
    int g = blockIdx.x;
    __shared__ float hg[HDIM];
    float invc = 1.0f / fmaxf(g_gcnt[g], 1.0f);
    for (int i = threadIdx.x; i < HDIM; i += blockDim.x)
        hg[i] = g_sums[g * HDIM + i] * invc;
    __syncthreads();
    int t = threadIdx.x;            // 128 threads: 0-63 mu, 64-127 logvar
    const float* W = (t < LDIM) ? Wmu : Wlv;
    const float* b = (t < LDIM) ? bmu : blv;
    int c = t & (LDIM - 1);
    float acc = b[c];
    #pragma unroll 8
    for (int k = 0; k < HDIM; k++)
        acc = fmaf(hg[k], W[k * LDIM + c], acc);
    float* o = (t < LDIM) ? out : (out + (size_t)G * LDIM);
    o[g * LDIM + c] = acc;
}

// ---------------- launch ----------------
extern "C" void kernel_launch(void* const* d_in, const int* in_sizes, int n_in,
                              void* d_out, int out_size) {
    const void* arr[11];
    int arr_sz[11];
    int na = 0;
    for (int i = 0; i < n_in && na < 11; i++) {
        if (in_sizes[i] == 1) continue;
        arr[na] = d_in[i];
        arr_sz[na] = in_sizes[i];
        na++;
    }
    const float* x     = (const float*)arr[0];
    const int*   edge  = (const int*)  arr[1];
    const int*   batch = (const int*)  arr[2];
    const float* W1    = (const float*)arr[3];
    const float* b1    = (const float*)arr[4];
    const float* W2    = (const float*)arr[5];
    const float* b2    = (const float*)arr[6];
    const float* Wmu   = (const float*)arr[7];
    const float* bmu   = (const float*)arr[8];
    const float* Wlv   = (const float*)arr[9];
    const float* blv   = (const float*)arr[10];

    const int N = arr_sz[2];          // batch has N elements
    const int E = arr_sz[1] / 2;      // edge_index is [2, E]
    const int G = NGRAPH;

    const int* src = edge;
    const int* dst = edge + E;

    void* p;
    cudaGetSymbolAddress(&p, g_bufA);   float* bufA = (float*)p;
    cudaGetSymbolAddress(&p, g_bufB);   float* bufB = (float*)p;
    void* p_counts; cudaGetSymbolAddress(&p_counts, g_counts);
    void* p_sums;   cudaGetSymbolAddress(&p_sums,   g_sums);
    void* p_gcnt;   cudaGetSymbolAddress(&p_gcnt,   g_gcnt);

    float* out = (float*)d_out;

    // 1. degree counts + dinv + CSR (+ per-edge weights)
    cudaMemsetAsync(p_counts, 0, (size_t)N * sizeof(int));
    k_count<<<(E + 255) / 256, 256>>>(dst, E);
    k_dinv<<<(N + 255) / 256, 256>>>(N);
    k_scan<<<1, 1024>>>(N, E);
    k_fill<<<(E + 255) / 256, 256>>>(src, dst, E);

    dim3 ggrid(2, (N + 127) / 128);

    // 2. layer 1: a = Agg(x) [N,128]; h1 = relu(a @ W1 + b1)  (agg commutes with W)
    {
        int blocks = (N + 3) / 4;
        k_agg<1><<<blocks, 128>>>(x, bufA, N);
    }
    k_gemm_mma<<<ggrid, 256>>>(bufA, W1, b1, bufB, N, FDIM);

    // 3. layer 2: a = Agg(h1) [N,256]; h2 = relu(a @ W2 + b2)
    {
        int blocks = (N + 3) / 4;
        k_agg<2><<<blocks, 128>>>(bufB, bufA, N);
    }
    k_gemm_mma<<<ggrid, 256>>>(bufA, W2, b2, bufB, N, HDIM);

    // 4. mean pool
    cudaMemsetAsync(p_sums, 0, (size_t)G * HDIM * sizeof(float));
    cudaMemsetAsync(p_gcnt, 0, (size_t)G * sizeof(float));
    k_pool<<<(N + POOL_CHUNK - 1) / POOL_CHUNK, 256>>>(bufB, batch, N);

    // 5. heads
    k_head<<<G, 128>>>(Wmu, bmu, Wlv, blv, out, G);
}